// round 1
// baseline (speedup 1.0000x reference)
#include <cuda_runtime.h>
#include <cuda_bf16.h>
#include <math.h>

#define N_NODES 20000
#define D_IN    128
#define E_RAW   320000
#define E_TOT   (E_RAW + N_NODES)   // 340000 (self-loops appended)
#define H1      8
#define C1      64
#define F1      512                  // H1*C1
#define F2      64
#define OUTF    32

// ---------------- scratch (static device globals; no allocation) -------------
__device__ float    g_xl1[(size_t)N_NODES * F1];
__device__ float    g_xr1[(size_t)N_NODES * F1];
__device__ float    g_h1 [(size_t)N_NODES * F1];
__device__ float    g_xl2[(size_t)N_NODES * F2];
__device__ float    g_xr2[(size_t)N_NODES * F2];
__device__ float    g_h2 [(size_t)N_NODES * F2];
__device__ float    g_sc1[(size_t)E_TOT * H1];
__device__ float    g_sc2[(size_t)E_TOT];
__device__ unsigned g_m1 [(size_t)N_NODES * H1];
__device__ float    g_den1[(size_t)N_NODES * H1];
__device__ unsigned g_m2 [N_NODES];
__device__ float    g_den2[N_NODES];
__device__ int      g_deg[N_NODES];
__device__ int      g_rowptr[N_NODES + 1];
__device__ int      g_cursor[N_NODES];
__device__ int      g_eidx[E_TOT];

// ---------------- helpers ----------------------------------------------------
__device__ __forceinline__ unsigned enc_f(float f) {
    unsigned u = __float_as_uint(f);
    return (u & 0x80000000u) ? ~u : (u | 0x80000000u);
}
__device__ __forceinline__ float dec_f(unsigned u) {
    return (u & 0x80000000u) ? __uint_as_float(u & 0x7fffffffu) : __uint_as_float(~u);
}
__device__ __forceinline__ float elu_f(float v) {
    return v > 0.0f ? v : (expf(v) - 1.0f);
}
__device__ __forceinline__ int e_src(const int* ei, int e) { return (e < E_RAW) ? ei[e] : (e - E_RAW); }
__device__ __forceinline__ int e_dst(const int* ei, int e) { return (e < E_RAW) ? ei[E_RAW + e] : (e - E_RAW); }

// ---------------- init / CSR build -------------------------------------------
__global__ void init_kernel() {
    int i = blockIdx.x * blockDim.x + threadIdx.x;
    int tot = N_NODES * H1;  // 160000 >= all the smaller arrays
    if (i < tot)     { g_m1[i] = 0u; g_den1[i] = 0.0f; }
    if (i < N_NODES) { g_m2[i] = 0u; g_den2[i] = 0.0f; g_deg[i] = 0; }
}

__global__ void count_kernel(const int* __restrict__ ei) {
    int e = blockIdx.x * blockDim.x + threadIdx.x;
    if (e >= E_TOT) return;
    atomicAdd(&g_deg[e_dst(ei, e)], 1);
}

__global__ void scan_kernel() {
    __shared__ int sh[1024];
    __shared__ int carry;
    if (threadIdx.x == 0) carry = 0;
    __syncthreads();
    for (int base = 0; base < N_NODES; base += 1024) {
        int i = base + threadIdx.x;
        int v = (i < N_NODES) ? g_deg[i] : 0;
        sh[threadIdx.x] = v;
        __syncthreads();
        for (int off = 1; off < 1024; off <<= 1) {
            int t = (threadIdx.x >= off) ? sh[threadIdx.x - off] : 0;
            __syncthreads();
            sh[threadIdx.x] += t;
            __syncthreads();
        }
        int excl = sh[threadIdx.x] - v + carry;
        if (i < N_NODES) { g_rowptr[i] = excl; g_cursor[i] = excl; }
        __syncthreads();
        if (threadIdx.x == 0) carry += sh[1023];
        __syncthreads();
    }
    if (threadIdx.x == 0) g_rowptr[N_NODES] = carry;
}

__global__ void scatter_kernel(const int* __restrict__ ei) {
    int e = blockIdx.x * blockDim.x + threadIdx.x;
    if (e >= E_TOT) return;
    int d = e_dst(ei, e);
    int pos = atomicAdd(&g_cursor[d], 1);
    g_eidx[pos] = e;
}

// ---------------- generic fp32 GEMM: C[M,N] = A[M,K] @ B[K,N] (+bias, act) ---
// BM=BN=64, BK=16, 256 threads, 4x4 per thread.
__global__ void gemm_kernel(const float* __restrict__ A, const float* __restrict__ B,
                            const float* __restrict__ bias, float* __restrict__ C,
                            int M, int N, int K, int act) {
    __shared__ float As[16][65];
    __shared__ float Bs[16][64];
    int tx = threadIdx.x & 15, ty = threadIdx.x >> 4;
    int bm = blockIdx.y * 64, bn = blockIdx.x * 64;
    float acc[4][4] = {};
    for (int k0 = 0; k0 < K; k0 += 16) {
        #pragma unroll
        for (int i = 0; i < 4; i++) {
            int idx = threadIdx.x + i * 256;
            int r = idx >> 4, c = idx & 15;
            int gr = bm + r;
            As[c][r] = (gr < M) ? A[(size_t)gr * K + (k0 + c)] : 0.0f;
        }
        #pragma unroll
        for (int i = 0; i < 4; i++) {
            int idx = threadIdx.x + i * 256;
            int r = idx >> 6, c = idx & 63;
            int gc = bn + c;
            Bs[r][c] = (gc < N) ? B[(size_t)(k0 + r) * N + gc] : 0.0f;
        }
        __syncthreads();
        #pragma unroll
        for (int kk = 0; kk < 16; kk++) {
            float a[4], b[4];
            #pragma unroll
            for (int i = 0; i < 4; i++) a[i] = As[kk][ty * 4 + i];
            #pragma unroll
            for (int j = 0; j < 4; j++) b[j] = Bs[kk][tx * 4 + j];
            #pragma unroll
            for (int i = 0; i < 4; i++)
                #pragma unroll
                for (int j = 0; j < 4; j++)
                    acc[i][j] += a[i] * b[j];
        }
        __syncthreads();
    }
    #pragma unroll
    for (int i = 0; i < 4; i++) {
        int gr = bm + ty * 4 + i;
        if (gr >= M) continue;
        #pragma unroll
        for (int j = 0; j < 4; j++) {
            int gc = bn + tx * 4 + j;
            if (gc >= N) continue;
            float v = acc[i][j] + (bias ? bias[gc] : 0.0f);
            if (act) v = elu_f(v);
            C[(size_t)gr * N + gc] = v;
        }
    }
}

// ---------------- layer 1 edge kernels ---------------------------------------
// warp per edge; 4 lanes per head; float4 channel chunks.
__global__ void score1_kernel(const int* __restrict__ ei, const float* __restrict__ att) {
    __shared__ __align__(16) float s_att[F1];
    for (int i = threadIdx.x; i < F1; i += blockDim.x) s_att[i] = att[i];
    __syncthreads();
    int warp = threadIdx.x >> 5, lane = threadIdx.x & 31;
    int e = blockIdx.x * 8 + warp;
    if (e >= E_TOT) return;
    int s = e_src(ei, e), d = e_dst(ei, e);
    int h = lane >> 2, t = lane & 3;
    const float4* xl4 = (const float4*)(g_xl1 + (size_t)s * F1);
    const float4* xr4 = (const float4*)(g_xr1 + (size_t)d * F1);
    const float4* at4 = (const float4*)s_att;
    float sum = 0.0f;
    #pragma unroll
    for (int k = 0; k < 4; k++) {
        int idx = h * 16 + t + k * 4;
        float4 a = xl4[idx], b = xr4[idx], w = at4[idx];
        float vx = a.x + b.x; vx = vx > 0.0f ? vx : 0.2f * vx;
        float vy = a.y + b.y; vy = vy > 0.0f ? vy : 0.2f * vy;
        float vz = a.z + b.z; vz = vz > 0.0f ? vz : 0.2f * vz;
        float vw = a.w + b.w; vw = vw > 0.0f ? vw : 0.2f * vw;
        sum += vx * w.x + vy * w.y + vz * w.z + vw * w.w;
    }
    sum += __shfl_xor_sync(0xffffffffu, sum, 1);
    sum += __shfl_xor_sync(0xffffffffu, sum, 2);
    if (t == 0) {
        g_sc1[(size_t)e * H1 + h] = sum;
        atomicMax(&g_m1[d * H1 + h], enc_f(sum));
    }
}

__global__ void expsum1_kernel(const int* __restrict__ ei) {
    int i = blockIdx.x * blockDim.x + threadIdx.x;
    if (i >= E_TOT * H1) return;
    int e = i >> 3, h = i & 7;
    int d = e_dst(ei, e);
    float m = dec_f(g_m1[d * H1 + h]);
    float a = expf(g_sc1[i] - m);
    g_sc1[i] = a;
    atomicAdd(&g_den1[d * H1 + h], a);
}

// block per node, warp per head; CSR gather (no float atomics)
__global__ void agg1_kernel(const int* __restrict__ ei, const float* __restrict__ b1) {
    int n = blockIdx.x;
    int h = threadIdx.x >> 5, lane = threadIdx.x & 31;
    int r0 = g_rowptr[n], r1 = g_rowptr[n + 1];
    float invd = 1.0f / g_den1[n * H1 + h];
    float acc0 = 0.0f, acc1 = 0.0f;
    for (int p = r0; p < r1; p++) {
        int e = g_eidx[p];
        int s = e_src(ei, e);
        float alpha = g_sc1[(size_t)e * H1 + h] * invd;
        const float* row = g_xl1 + (size_t)s * F1 + h * C1;
        acc0 += alpha * row[lane];
        acc1 += alpha * row[lane + 32];
    }
    int c0 = h * C1 + lane;
    float v0 = acc0 + b1[c0];
    float v1 = acc1 + b1[c0 + 32];
    g_h1[(size_t)n * F1 + c0]      = elu_f(v0);
    g_h1[(size_t)n * F1 + c0 + 32] = elu_f(v1);
}

// ---------------- layer 2 edge kernels (H=1, C=64) ---------------------------
__global__ void score2_kernel(const int* __restrict__ ei, const float* __restrict__ att) {
    int warp = threadIdx.x >> 5, lane = threadIdx.x & 31;
    int e = blockIdx.x * 8 + warp;
    if (e >= E_TOT) return;
    int s = e_src(ei, e), d = e_dst(ei, e);
    const float* xl = g_xl2 + (size_t)s * F2;
    const float* xr = g_xr2 + (size_t)d * F2;
    float v0 = xl[lane] + xr[lane];           v0 = v0 > 0.0f ? v0 : 0.2f * v0;
    float v1 = xl[lane + 32] + xr[lane + 32]; v1 = v1 > 0.0f ? v1 : 0.2f * v1;
    float sum = v0 * att[lane] + v1 * att[lane + 32];
    #pragma unroll
    for (int off = 16; off > 0; off >>= 1) sum += __shfl_xor_sync(0xffffffffu, sum, off);
    if (lane == 0) {
        g_sc2[e] = sum;
        atomicMax(&g_m2[d], enc_f(sum));
    }
}

__global__ void expsum2_kernel(const int* __restrict__ ei) {
    int e = blockIdx.x * blockDim.x + threadIdx.x;
    if (e >= E_TOT) return;
    int d = e_dst(ei, e);
    float a = expf(g_sc2[e] - dec_f(g_m2[d]));
    g_sc2[e] = a;
    atomicAdd(&g_den2[d], a);
}

__global__ void agg2_kernel(const int* __restrict__ ei, const float* __restrict__ b2) {
    int warp = threadIdx.x >> 5, lane = threadIdx.x & 31;
    int n = blockIdx.x * 8 + warp;
    if (n >= N_NODES) return;
    int r0 = g_rowptr[n], r1 = g_rowptr[n + 1];
    float invd = 1.0f / g_den2[n];
    float acc0 = 0.0f, acc1 = 0.0f;
    for (int p = r0; p < r1; p++) {
        int e = g_eidx[p];
        int s = e_src(ei, e);
        float alpha = g_sc2[e] * invd;
        const float* row = g_xl2 + (size_t)s * F2;
        acc0 += alpha * row[lane];
        acc1 += alpha * row[lane + 32];
    }
    float v0 = acc0 + b2[lane];
    float v1 = acc1 + b2[lane + 32];
    g_h2[(size_t)n * F2 + lane]      = elu_f(v0);
    g_h2[(size_t)n * F2 + lane + 32] = elu_f(v1);
}

// ---------------- launch -----------------------------------------------------
extern "C" void kernel_launch(void* const* d_in, const int* in_sizes, int n_in,
                              void* d_out, int out_size) {
    const float* x    = (const float*)d_in[0];
    const int*   ei   = (const int*)  d_in[1];
    const float* W1l  = (const float*)d_in[2];
    const float* W1r  = (const float*)d_in[3];
    const float* att1 = (const float*)d_in[4];
    const float* b1   = (const float*)d_in[5];
    const float* W2l  = (const float*)d_in[6];
    const float* W2r  = (const float*)d_in[7];
    const float* att2 = (const float*)d_in[8];
    const float* b2   = (const float*)d_in[9];
    const float* Wlin = (const float*)d_in[10];
    const float* blin = (const float*)d_in[11];
    float* out = (float*)d_out;

    float *p_xl1, *p_xr1, *p_h1, *p_xl2, *p_xr2, *p_h2;
    cudaGetSymbolAddress((void**)&p_xl1, g_xl1);
    cudaGetSymbolAddress((void**)&p_xr1, g_xr1);
    cudaGetSymbolAddress((void**)&p_h1,  g_h1);
    cudaGetSymbolAddress((void**)&p_xl2, g_xl2);
    cudaGetSymbolAddress((void**)&p_xr2, g_xr2);
    cudaGetSymbolAddress((void**)&p_h2,  g_h2);

    // CSR build + stat init
    init_kernel<<<(N_NODES * H1 + 255) / 256, 256>>>();
    count_kernel<<<(E_TOT + 255) / 256, 256>>>(ei);
    scan_kernel<<<1, 1024>>>();
    scatter_kernel<<<(E_TOT + 255) / 256, 256>>>(ei);

    // Layer 1
    dim3 g1(F1 / 64, (N_NODES + 63) / 64);
    gemm_kernel<<<g1, 256>>>(x, W1l, nullptr, p_xl1, N_NODES, F1, D_IN, 0);
    gemm_kernel<<<g1, 256>>>(x, W1r, nullptr, p_xr1, N_NODES, F1, D_IN, 0);
    score1_kernel<<<(E_TOT + 7) / 8, 256>>>(ei, att1);
    expsum1_kernel<<<(E_TOT * H1 + 255) / 256, 256>>>(ei);
    agg1_kernel<<<N_NODES, 256>>>(ei, b1);

    // Layer 2
    dim3 g2(1, (N_NODES + 63) / 64);
    gemm_kernel<<<g2, 256>>>(p_h1, W2l, nullptr, p_xl2, N_NODES, F2, F1, 0);
    gemm_kernel<<<g2, 256>>>(p_h1, W2r, nullptr, p_xr2, N_NODES, F2, F1, 0);
    score2_kernel<<<(E_TOT + 7) / 8, 256>>>(ei, att2);
    expsum2_kernel<<<(E_TOT + 255) / 256, 256>>>(ei);
    agg2_kernel<<<(N_NODES + 7) / 8, 256>>>(ei, b2);

    // Final linear + elu -> out
    dim3 g3(1, (N_NODES + 63) / 64);
    gemm_kernel<<<g3, 256>>>(p_h2, Wlin, blin, out, N_NODES, OUTF, F2, 1);
}

// round 3
// speedup vs baseline: 1.5409x; 1.5409x over previous
#include <cuda_runtime.h>
#include <cuda_bf16.h>
#include <math.h>

#define N_NODES 20000
#define D_IN    128
#define E_RAW   320000
#define E_TOT   (E_RAW + N_NODES)   // self-loops appended
#define H1      8
#define C1      64
#define F1      512
#define F2      64
#define OUTF    32

// ---------------- scratch (static device globals) ----------------------------
__device__ float g_xl1[(size_t)N_NODES * F1];
__device__ float g_xr1[(size_t)N_NODES * F1];
__device__ float g_h1 [(size_t)N_NODES * F1];
__device__ float g_xl2[(size_t)N_NODES * F2];
__device__ float g_xr2[(size_t)N_NODES * F2];
__device__ int   g_deg[N_NODES];
__device__ int   g_rowptr[N_NODES + 1];
__device__ int   g_cursor[N_NODES];
__device__ int   g_eidx[E_TOT];

__device__ __forceinline__ int e_dst(const int* ei, int e) {
    return (e < E_RAW) ? ei[E_RAW + e] : (e - E_RAW);
}

// ---------------- CSR build ---------------------------------------------------
__global__ void init_deg_kernel() {
    int i = blockIdx.x * blockDim.x + threadIdx.x;
    if (i < N_NODES) g_deg[i] = 0;
}

__global__ void count_kernel(const int* __restrict__ ei) {
    int e = blockIdx.x * blockDim.x + threadIdx.x;
    if (e >= E_TOT) return;
    atomicAdd(&g_deg[e_dst(ei, e)], 1);
}

__global__ void scan_kernel() {
    __shared__ int sh[1024];
    __shared__ int carry;
    if (threadIdx.x == 0) carry = 0;
    __syncthreads();
    for (int base = 0; base < N_NODES; base += 1024) {
        int i = base + threadIdx.x;
        int v = (i < N_NODES) ? g_deg[i] : 0;
        sh[threadIdx.x] = v;
        __syncthreads();
        for (int off = 1; off < 1024; off <<= 1) {
            int t = (threadIdx.x >= off) ? sh[threadIdx.x - off] : 0;
            __syncthreads();
            sh[threadIdx.x] += t;
            __syncthreads();
        }
        int excl = sh[threadIdx.x] - v + carry;
        if (i < N_NODES) { g_rowptr[i] = excl; g_cursor[i] = excl; }
        __syncthreads();
        if (threadIdx.x == 0) carry += sh[1023];
        __syncthreads();
    }
    if (threadIdx.x == 0) g_rowptr[N_NODES] = carry;
}

__global__ void scatter_kernel(const int* __restrict__ ei) {
    int e = blockIdx.x * blockDim.x + threadIdx.x;
    if (e >= E_TOT) return;
    int d = e_dst(ei, e);
    int pos = atomicAdd(&g_cursor[d], 1);
    g_eidx[pos] = e;
}

// ---------------- dual fp32 GEMM with f32x2 packed FMA ------------------------
// Cm{a,b}[Mm,Nn] = Aa[Mm,Kk] @ Bb{a,b}[Kk,Nn].  BM=128, BN=64, BK=16,
// 256 threads, 8x4 per thread, accumulators packed pairwise along M (f32x2).
__global__ void gemm_dual(const float* __restrict__ Aa,
                          const float* __restrict__ Ba, const float* __restrict__ Bb,
                          float* __restrict__ Ca, float* __restrict__ Cb,
                          int Mm, int Nn, int Kk, int nbx)
{
    const float* Bp; float* Cp; int bn;
    if ((int)blockIdx.x < nbx) { Bp = Ba; Cp = Ca; bn = blockIdx.x * 64; }
    else                       { Bp = Bb; Cp = Cb; bn = (blockIdx.x - nbx) * 64; }
    int bm = blockIdx.y * 128;

    __shared__ float As[16][128];   // transposed: As[k][m]
    __shared__ float Bs[16][64];

    int tid = threadIdx.x;
    int tx = tid & 15, ty = tid >> 4;

    int ar = tid >> 1;            // 0..127 (row within tile)
    int ak = (tid & 1) * 8;       // 0 or 8 (k offset)
    int bk = tid >> 4;            // 0..15
    int bc = (tid & 15) * 4;      // 0..60

    const float* Aptr = Aa + (size_t)(bm + ar) * Kk;
    bool arow_ok = (bm + ar) < Mm;
    int nk = Kk >> 4;

    float4 pa0, pa1, pb;
    if (arow_ok) { pa0 = *(const float4*)(Aptr + ak); pa1 = *(const float4*)(Aptr + ak + 4); }
    else { pa0 = make_float4(0.f,0.f,0.f,0.f); pa1 = pa0; }
    pb = *(const float4*)(Bp + (size_t)bk * Nn + bn + bc);

    unsigned long long acc[4][4];
    #pragma unroll
    for (int i = 0; i < 4; i++)
        #pragma unroll
        for (int j = 0; j < 4; j++) acc[i][j] = 0ull;

    for (int kt = 0; kt < nk; kt++) {
        As[ak+0][ar] = pa0.x; As[ak+1][ar] = pa0.y; As[ak+2][ar] = pa0.z; As[ak+3][ar] = pa0.w;
        As[ak+4][ar] = pa1.x; As[ak+5][ar] = pa1.y; As[ak+6][ar] = pa1.z; As[ak+7][ar] = pa1.w;
        *(float4*)&Bs[bk][bc] = pb;
        __syncthreads();
        if (kt + 1 < nk) {
            int k0 = (kt + 1) << 4;
            if (arow_ok) { pa0 = *(const float4*)(Aptr + k0 + ak); pa1 = *(const float4*)(Aptr + k0 + ak + 4); }
            pb = *(const float4*)(Bp + (size_t)(k0 + bk) * Nn + bn + bc);
        }
        #pragma unroll
        for (int kk = 0; kk < 16; kk++) {
            ulonglong2 a01 = *(const ulonglong2*)&As[kk][ty * 8];
            ulonglong2 a23 = *(const ulonglong2*)&As[kk][ty * 8 + 4];
            float4 b4 = *(const float4*)&Bs[kk][tx * 4];
            unsigned long long ap[4] = {a01.x, a01.y, a23.x, a23.y};
            unsigned long long bp[4];
            asm("mov.b64 %0, {%1, %1};" : "=l"(bp[0]) : "f"(b4.x));
            asm("mov.b64 %0, {%1, %1};" : "=l"(bp[1]) : "f"(b4.y));
            asm("mov.b64 %0, {%1, %1};" : "=l"(bp[2]) : "f"(b4.z));
            asm("mov.b64 %0, {%1, %1};" : "=l"(bp[3]) : "f"(b4.w));
            #pragma unroll
            for (int i = 0; i < 4; i++)
                #pragma unroll
                for (int j = 0; j < 4; j++)
                    asm("fma.rn.f32x2 %0, %1, %2, %0;" : "+l"(acc[i][j]) : "l"(ap[i]), "l"(bp[j]));
        }
        __syncthreads();
    }

    #pragma unroll
    for (int ip = 0; ip < 4; ip++) {
        float lo[4], hi[4];
        #pragma unroll
        for (int j = 0; j < 4; j++)
            asm("mov.b64 {%0, %1}, %2;" : "=f"(lo[j]), "=f"(hi[j]) : "l"(acc[ip][j]));
        int gr0 = bm + ty * 8 + ip * 2;
        if (gr0 < Mm)
            *(float4*)(Cp + (size_t)gr0 * Nn + bn + tx * 4) = make_float4(lo[0], lo[1], lo[2], lo[3]);
        if (gr0 + 1 < Mm)
            *(float4*)(Cp + (size_t)(gr0 + 1) * Nn + bn + tx * 4) = make_float4(hi[0], hi[1], hi[2], hi[3]);
    }
}

// ---------------- fused GAT layer 1 (block per node, warp per head) -----------
// Online-softmax over CSR in-edges; xl rows read once, used for score AND agg.
__global__ void gat1_kernel(const int* __restrict__ ei, const float* __restrict__ att,
                            const float* __restrict__ b1)
{
    int n = blockIdx.x;
    int w = threadIdx.x >> 5, l = threadIdx.x & 31;
    int c0 = w * 64 + l, c1 = c0 + 32;

    float xr0 = g_xr1[(size_t)n * F1 + c0];
    float xr1v = g_xr1[(size_t)n * F1 + c1];
    float at0 = att[c0], at1 = att[c1];

    int r0 = g_rowptr[n], r1 = g_rowptr[n + 1];
    float m = -INFINITY, den = 0.f, acc0 = 0.f, acc1 = 0.f;

    for (int p = r0; p < r1; p++) {
        int e = g_eidx[p];
        int s = (e < E_RAW) ? ei[e] : (e - E_RAW);
        float xl0 = g_xl1[(size_t)s * F1 + c0];
        float xl1v = g_xl1[(size_t)s * F1 + c1];
        float v0 = xl0 + xr0;  v0 = v0 > 0.f ? v0 : 0.2f * v0;
        float v1 = xl1v + xr1v; v1 = v1 > 0.f ? v1 : 0.2f * v1;
        float sc = v0 * at0 + v1 * at1;
        #pragma unroll
        for (int o = 16; o > 0; o >>= 1) sc += __shfl_xor_sync(0xffffffffu, sc, o);
        if (sc > m) {
            float r = __expf(m - sc);
            den *= r; acc0 *= r; acc1 *= r; m = sc;
        }
        float a = __expf(sc - m);
        den += a; acc0 += a * xl0; acc1 += a * xl1v;
    }

    float invd = 1.0f / den;
    float o0 = acc0 * invd + b1[c0];
    float o1 = acc1 * invd + b1[c1];
    g_h1[(size_t)n * F1 + c0] = o0 > 0.f ? o0 : __expf(o0) - 1.f;
    g_h1[(size_t)n * F1 + c1] = o1 > 0.f ? o1 : __expf(o1) - 1.f;
}

// ---------------- fused GAT layer 2 + final linear + elu ----------------------
// Warp per node (8 nodes/block). Epilogue does h2[64] @ Wlin[64,32] via smem.
__global__ void gat2_kernel(const int* __restrict__ ei, const float* __restrict__ att,
                            const float* __restrict__ b2,
                            const float* __restrict__ Wlin, const float* __restrict__ blin,
                            float* __restrict__ out)
{
    __shared__ float sW[64 * 32];
    __shared__ float sb[32];
    __shared__ float sh2[8][64];
    for (int i = threadIdx.x; i < 64 * 32; i += 256) sW[i] = Wlin[i];
    if (threadIdx.x < 32) sb[threadIdx.x] = blin[threadIdx.x];
    __syncthreads();

    int w = threadIdx.x >> 5, l = threadIdx.x & 31;
    int n = blockIdx.x * 8 + w;

    float xr0 = g_xr2[(size_t)n * F2 + l];
    float xr1v = g_xr2[(size_t)n * F2 + l + 32];
    float at0 = att[l], at1 = att[l + 32];

    int r0 = g_rowptr[n], r1 = g_rowptr[n + 1];
    float m = -INFINITY, den = 0.f, acc0 = 0.f, acc1 = 0.f;

    for (int p = r0; p < r1; p++) {
        int e = g_eidx[p];
        int s = (e < E_RAW) ? ei[e] : (e - E_RAW);
        float xl0 = g_xl2[(size_t)s * F2 + l];
        float xl1v = g_xl2[(size_t)s * F2 + l + 32];
        float v0 = xl0 + xr0;  v0 = v0 > 0.f ? v0 : 0.2f * v0;
        float v1 = xl1v + xr1v; v1 = v1 > 0.f ? v1 : 0.2f * v1;
        float sc = v0 * at0 + v1 * at1;
        #pragma unroll
        for (int o = 16; o > 0; o >>= 1) sc += __shfl_xor_sync(0xffffffffu, sc, o);
        if (sc > m) {
            float r = __expf(m - sc);
            den *= r; acc0 *= r; acc1 *= r; m = sc;
        }
        float a = __expf(sc - m);
        den += a; acc0 += a * xl0; acc1 += a * xl1v;
    }

    float invd = 1.0f / den;
    float h0 = acc0 * invd + b2[l];      h0 = h0 > 0.f ? h0 : __expf(h0) - 1.f;
    float h1 = acc1 * invd + b2[l + 32]; h1 = h1 > 0.f ? h1 : __expf(h1) - 1.f;
    sh2[w][l] = h0; sh2[w][l + 32] = h1;
    __syncwarp();

    float o = sb[l];
    #pragma unroll
    for (int k = 0; k < 64; k++) o += sh2[w][k] * sW[k * 32 + l];
    out[(size_t)n * OUTF + l] = o > 0.f ? o : __expf(o) - 1.f;
}

// ---------------- launch ------------------------------------------------------
extern "C" void kernel_launch(void* const* d_in, const int* in_sizes, int n_in,
                              void* d_out, int out_size) {
    const float* x    = (const float*)d_in[0];
    const int*   ei   = (const int*)  d_in[1];
    const float* W1l  = (const float*)d_in[2];
    const float* W1r  = (const float*)d_in[3];
    const float* att1 = (const float*)d_in[4];
    const float* b1   = (const float*)d_in[5];
    const float* W2l  = (const float*)d_in[6];
    const float* W2r  = (const float*)d_in[7];
    const float* att2 = (const float*)d_in[8];
    const float* b2   = (const float*)d_in[9];
    const float* Wlin = (const float*)d_in[10];
    const float* blin = (const float*)d_in[11];
    float* out = (float*)d_out;

    float *p_xl1, *p_xr1, *p_h1, *p_xl2, *p_xr2;
    cudaGetSymbolAddress((void**)&p_xl1, g_xl1);
    cudaGetSymbolAddress((void**)&p_xr1, g_xr1);
    cudaGetSymbolAddress((void**)&p_h1,  g_h1);
    cudaGetSymbolAddress((void**)&p_xl2, g_xl2);
    cudaGetSymbolAddress((void**)&p_xr2, g_xr2);

    // CSR build
    init_deg_kernel<<<(N_NODES + 255) / 256, 256>>>();
    count_kernel<<<(E_TOT + 255) / 256, 256>>>(ei);
    scan_kernel<<<1, 1024>>>();
    scatter_kernel<<<(E_TOT + 255) / 256, 256>>>(ei);

    // Layer 1: xl1 = x@W1l, xr1 = x@W1r (one dual launch)
    dim3 g1(16, (N_NODES + 127) / 128);
    gemm_dual<<<g1, 256>>>(x, W1l, W1r, p_xl1, p_xr1, N_NODES, F1, D_IN, 8);
    gat1_kernel<<<N_NODES, 256>>>(ei, att1, b1);

    // Layer 2: xl2 = h1@W2l, xr2 = h1@W2r
    dim3 g2(2, (N_NODES + 127) / 128);
    gemm_dual<<<g2, 256>>>(p_h1, W2l, W2r, p_xl2, p_xr2, N_NODES, F2, F1, 1);
    gat2_kernel<<<N_NODES / 8, 256>>>(ei, att2, b2, Wlin, blin, out);
}

// round 5
// speedup vs baseline: 1.7392x; 1.1287x over previous
#include <cuda_runtime.h>
#include <cuda_bf16.h>
#include <math.h>
#include <stdint.h>

#define N_NODES 20000
#define D_IN    128
#define E_RAW   320000
#define E_TOT   (E_RAW + N_NODES)
#define F1      512
#define F2      64
#define OUTF    32

// ---------------- scratch ----------------------------------------------------
__device__ float g_xl1[(size_t)N_NODES * F1];
__device__ float g_xr1[(size_t)N_NODES * F1];
__device__ float g_xl2[(size_t)N_NODES * F2];
__device__ float g_xr2[(size_t)N_NODES * F2];
__device__ int   g_deg[N_NODES];
__device__ int   g_rowptr[N_NODES + 1];
__device__ int   g_cursor[N_NODES];
__device__ int   g_eidx[E_TOT];
// split-bf16 operands
__device__ __nv_bfloat16 g_xh  [(size_t)N_NODES * D_IN];
__device__ __nv_bfloat16 g_xlo [(size_t)N_NODES * D_IN];
__device__ __nv_bfloat16 g_h1h [(size_t)N_NODES * F1];
__device__ __nv_bfloat16 g_h1lo[(size_t)N_NODES * F1];
__device__ __nv_bfloat16 g_w1h [2 * F1 * D_IN];   // [w][n][k]
__device__ __nv_bfloat16 g_w1lo[2 * F1 * D_IN];
__device__ __nv_bfloat16 g_w2h [2 * F2 * F1];     // [w][n][k]
__device__ __nv_bfloat16 g_w2lo[2 * F2 * F1];

__device__ __forceinline__ int e_dst(const int* ei, int e) {
    return (e < E_RAW) ? ei[E_RAW + e] : (e - E_RAW);
}

// ---------------- CSR build --------------------------------------------------
__global__ void init_deg_kernel() {
    int i = blockIdx.x * blockDim.x + threadIdx.x;
    if (i < N_NODES) g_deg[i] = 0;
}
__global__ void count_kernel(const int* __restrict__ ei) {
    int e = blockIdx.x * blockDim.x + threadIdx.x;
    if (e >= E_TOT) return;
    atomicAdd(&g_deg[e_dst(ei, e)], 1);
}
__global__ void scan_kernel() {
    __shared__ int sh[1024];
    __shared__ int carry;
    if (threadIdx.x == 0) carry = 0;
    __syncthreads();
    for (int base = 0; base < N_NODES; base += 1024) {
        int i = base + threadIdx.x;
        int v = (i < N_NODES) ? g_deg[i] : 0;
        sh[threadIdx.x] = v;
        __syncthreads();
        for (int off = 1; off < 1024; off <<= 1) {
            int t = (threadIdx.x >= off) ? sh[threadIdx.x - off] : 0;
            __syncthreads();
            sh[threadIdx.x] += t;
            __syncthreads();
        }
        int excl = sh[threadIdx.x] - v + carry;
        if (i < N_NODES) { g_rowptr[i] = excl; g_cursor[i] = excl; }
        __syncthreads();
        if (threadIdx.x == 0) carry += sh[1023];
        __syncthreads();
    }
    if (threadIdx.x == 0) g_rowptr[N_NODES] = carry;
}
__global__ void scatter_kernel(const int* __restrict__ ei) {
    int e = blockIdx.x * blockDim.x + threadIdx.x;
    if (e >= E_TOT) return;
    int d = e_dst(ei, e);
    int pos = atomicAdd(&g_cursor[d], 1);
    g_eidx[pos] = e;
}

// ---------------- fp32 -> split bf16 (hi + lo) --------------------------------
__device__ __forceinline__ void split2(float v, __nv_bfloat16* ph, __nv_bfloat16* pl) {
    __nv_bfloat16 h = __float2bfloat16(v);
    *ph = h;
    *pl = __float2bfloat16(v - __bfloat162float(h));
}
__global__ void split_x_kernel(const float* __restrict__ x) {
    int i = blockIdx.x * blockDim.x + threadIdx.x;
    if (i >= N_NODES * D_IN) return;
    split2(x[i], &g_xh[i], &g_xlo[i]);
}
// W1 [128,512] row-major -> [n][k]
__global__ void split_w1_kernel(const float* __restrict__ Wl, const float* __restrict__ Wr) {
    int i = blockIdx.x * blockDim.x + threadIdx.x;
    if (i >= F1 * D_IN) return;
    int k = i / F1, n = i % F1;
    split2(Wl[i], &g_w1h[n * D_IN + k], &g_w1lo[n * D_IN + k]);
    split2(Wr[i], &g_w1h[F1 * D_IN + n * D_IN + k], &g_w1lo[F1 * D_IN + n * D_IN + k]);
}
// W2 [512,64] row-major -> [n][k]
__global__ void split_w2_kernel(const float* __restrict__ Wl, const float* __restrict__ Wr) {
    int i = blockIdx.x * blockDim.x + threadIdx.x;
    if (i >= F2 * F1) return;
    int k = i / F2, n = i % F2;
    split2(Wl[i], &g_w2h[n * F1 + k], &g_w2lo[n * F1 + k]);
    split2(Wr[i], &g_w2h[F2 * F1 + n * F1 + k], &g_w2lo[F2 * F1 + n * F1 + k]);
}

// ---------------- split-bf16 GEMM on mma.sync (HMMA) --------------------------
// C_w[M,N] = A[M,K] @ B_w[K,N],  A = Ah+Al (row-major [m][k] bf16),
// B given transposed [w][n][k] bf16 (Bh+Bl). Computes hh + hl + lh.
// BM=128, BN=64, BK=32; 8 warps (4 M x 2 N), warp tile 32x32 of m16n8k16.
#define SPAD 40   // smem row stride in bf16 (80B = 20 banks -> conflict-free)

__device__ __forceinline__ uint32_t lds_u32(const __nv_bfloat16* s, int row, int col) {
    return *(const uint32_t*)((const char*)s + row * (SPAD * 2) + col * 2);
}
__device__ __forceinline__ void mma_bf16(float* c, const uint32_t* a, const uint32_t* b) {
    asm volatile(
        "mma.sync.aligned.m16n8k16.row.col.f32.bf16.bf16.f32 "
        "{%0,%1,%2,%3}, {%4,%5,%6,%7}, {%8,%9}, {%0,%1,%2,%3};"
        : "+f"(c[0]), "+f"(c[1]), "+f"(c[2]), "+f"(c[3])
        : "r"(a[0]), "r"(a[1]), "r"(a[2]), "r"(a[3]), "r"(b[0]), "r"(b[1]));
}

__global__ void __launch_bounds__(256) gemm_mma(
    const __nv_bfloat16* __restrict__ Ah, const __nv_bfloat16* __restrict__ Al,
    const __nv_bfloat16* __restrict__ Bh, const __nv_bfloat16* __restrict__ Bl,
    float* __restrict__ C0, float* __restrict__ C1,
    int M, int N, int K, int ntPerW)
{
    __shared__ __nv_bfloat16 sAh[128 * SPAD], sAl[128 * SPAD];
    __shared__ __nv_bfloat16 sBh[64 * SPAD],  sBl[64 * SPAD];

    int tid = threadIdx.x;
    int wid = tid >> 5, lane = tid & 31;
    int w  = blockIdx.x / ntPerW;
    int nt = blockIdx.x % ntPerW;
    int bm = blockIdx.y * 128;

    const __nv_bfloat16* Bth = Bh + (size_t)w * N * K + (size_t)(nt * 64) * K;
    const __nv_bfloat16* Btl = Bl + (size_t)w * N * K + (size_t)(nt * 64) * K;
    float* C = w ? C1 : C0;

    int wm = wid & 3, wn = wid >> 2;
    int g = lane >> 2, t2 = (lane & 3) * 2;

    float acc[2][4][4];
    #pragma unroll
    for (int i = 0; i < 2; i++)
        #pragma unroll
        for (int j = 0; j < 4; j++)
            #pragma unroll
            for (int q = 0; q < 4; q++) acc[i][j][q] = 0.f;

    int nk = K >> 5;
    for (int kt = 0; kt < nk; kt++) {
        int k0 = kt << 5;
        // stage A (128x32, hi+lo): 512 uint4 each -> 2 per thread
        #pragma unroll
        for (int p = 0; p < 2; p++) {
            int idx = tid + p * 256;
            int r = idx >> 2, q = idx & 3;
            int gm = bm + r;
            uint4 vh = make_uint4(0, 0, 0, 0), vl = vh;
            if (gm < M) {
                vh = *(const uint4*)(Ah + (size_t)gm * K + k0 + q * 8);
                vl = *(const uint4*)(Al + (size_t)gm * K + k0 + q * 8);
            }
            *(uint4*)((char*)sAh + r * (SPAD * 2) + q * 16) = vh;
            *(uint4*)((char*)sAl + r * (SPAD * 2) + q * 16) = vl;
        }
        // stage B (64x32, hi+lo): 256 uint4 each -> 1 per thread
        {
            int r = tid >> 2, q = tid & 3;
            *(uint4*)((char*)sBh + r * (SPAD * 2) + q * 16) =
                *(const uint4*)(Bth + (size_t)r * K + k0 + q * 8);
            *(uint4*)((char*)sBl + r * (SPAD * 2) + q * 16) =
                *(const uint4*)(Btl + (size_t)r * K + k0 + q * 8);
        }
        __syncthreads();

        #pragma unroll
        for (int kk = 0; kk < 32; kk += 16) {
            uint32_t ah[2][4], al[2][4], bhf[4][2], blf[4][2];
            #pragma unroll
            for (int i = 0; i < 2; i++) {
                int r = wm * 32 + i * 16;
                ah[i][0] = lds_u32(sAh, r + g,     kk + t2);
                ah[i][1] = lds_u32(sAh, r + g + 8, kk + t2);
                ah[i][2] = lds_u32(sAh, r + g,     kk + t2 + 8);
                ah[i][3] = lds_u32(sAh, r + g + 8, kk + t2 + 8);
                al[i][0] = lds_u32(sAl, r + g,     kk + t2);
                al[i][1] = lds_u32(sAl, r + g + 8, kk + t2);
                al[i][2] = lds_u32(sAl, r + g,     kk + t2 + 8);
                al[i][3] = lds_u32(sAl, r + g + 8, kk + t2 + 8);
            }
            #pragma unroll
            for (int j = 0; j < 4; j++) {
                int n = wn * 32 + j * 8 + g;
                bhf[j][0] = lds_u32(sBh, n, kk + t2);
                bhf[j][1] = lds_u32(sBh, n, kk + t2 + 8);
                blf[j][0] = lds_u32(sBl, n, kk + t2);
                blf[j][1] = lds_u32(sBl, n, kk + t2 + 8);
            }
            #pragma unroll
            for (int i = 0; i < 2; i++)
                #pragma unroll
                for (int j = 0; j < 4; j++) {
                    mma_bf16(acc[i][j], ah[i], bhf[j]);
                    mma_bf16(acc[i][j], ah[i], blf[j]);
                    mma_bf16(acc[i][j], al[i], bhf[j]);
                }
        }
        __syncthreads();
    }

    // epilogue
    #pragma unroll
    for (int i = 0; i < 2; i++) {
        int r0 = bm + wm * 32 + i * 16 + g;
        #pragma unroll
        for (int j = 0; j < 4; j++) {
            int c = nt * 64 + wn * 32 + j * 8 + t2;
            if (r0 < M)
                *(float2*)(C + (size_t)r0 * N + c) = make_float2(acc[i][j][0], acc[i][j][1]);
            if (r0 + 8 < M)
                *(float2*)(C + (size_t)(r0 + 8) * N + c) = make_float2(acc[i][j][2], acc[i][j][3]);
        }
    }
}

// ---------------- fused GAT layer 1 (block/node, warp/head) -------------------
__global__ void gat1_kernel(const int* __restrict__ ei, const float* __restrict__ att,
                            const float* __restrict__ b1)
{
    int n = blockIdx.x;
    int w = threadIdx.x >> 5, l = threadIdx.x & 31;
    int c0 = w * 64 + l, c1 = c0 + 32;

    float xr0 = g_xr1[(size_t)n * F1 + c0];
    float xr1v = g_xr1[(size_t)n * F1 + c1];
    float at0 = att[c0], at1 = att[c1];

    int r0 = g_rowptr[n], r1 = g_rowptr[n + 1];
    float m = -INFINITY, den = 0.f, acc0 = 0.f, acc1 = 0.f;

    for (int p = r0; p < r1; p++) {
        int e = g_eidx[p];
        int s = (e < E_RAW) ? ei[e] : (e - E_RAW);
        float xl0 = g_xl1[(size_t)s * F1 + c0];
        float xl1v = g_xl1[(size_t)s * F1 + c1];
        float v0 = xl0 + xr0;  v0 = v0 > 0.f ? v0 : 0.2f * v0;
        float v1 = xl1v + xr1v; v1 = v1 > 0.f ? v1 : 0.2f * v1;
        float sc = v0 * at0 + v1 * at1;
        #pragma unroll
        for (int o = 16; o > 0; o >>= 1) sc += __shfl_xor_sync(0xffffffffu, sc, o);
        if (sc > m) {
            float r = __expf(m - sc);
            den *= r; acc0 *= r; acc1 *= r; m = sc;
        }
        float a = __expf(sc - m);
        den += a; acc0 += a * xl0; acc1 += a * xl1v;
    }

    float invd = 1.0f / den;
    float o0 = acc0 * invd + b1[c0];
    float o1 = acc1 * invd + b1[c1];
    o0 = o0 > 0.f ? o0 : __expf(o0) - 1.f;
    o1 = o1 > 0.f ? o1 : __expf(o1) - 1.f;
    // emit split bf16 directly for the layer-2 tensor GEMM
    split2(o0, &g_h1h[(size_t)n * F1 + c0], &g_h1lo[(size_t)n * F1 + c0]);
    split2(o1, &g_h1h[(size_t)n * F1 + c1], &g_h1lo[(size_t)n * F1 + c1]);
}

// ---------------- fused GAT layer 2 + linear + elu ----------------------------
__global__ void gat2_kernel(const int* __restrict__ ei, const float* __restrict__ att,
                            const float* __restrict__ b2,
                            const float* __restrict__ Wlin, const float* __restrict__ blin,
                            float* __restrict__ out)
{
    __shared__ float sW[64 * 32];
    __shared__ float sb[32];
    __shared__ float sh2[8][64];
    for (int i = threadIdx.x; i < 64 * 32; i += 256) sW[i] = Wlin[i];
    if (threadIdx.x < 32) sb[threadIdx.x] = blin[threadIdx.x];
    __syncthreads();

    int w = threadIdx.x >> 5, l = threadIdx.x & 31;
    int n = blockIdx.x * 8 + w;

    float xr0 = g_xr2[(size_t)n * F2 + l];
    float xr1v = g_xr2[(size_t)n * F2 + l + 32];
    float at0 = att[l], at1 = att[l + 32];

    int r0 = g_rowptr[n], r1 = g_rowptr[n + 1];
    float m = -INFINITY, den = 0.f, acc0 = 0.f, acc1 = 0.f;

    for (int p = r0; p < r1; p++) {
        int e = g_eidx[p];
        int s = (e < E_RAW) ? ei[e] : (e - E_RAW);
        float xl0 = g_xl2[(size_t)s * F2 + l];
        float xl1v = g_xl2[(size_t)s * F2 + l + 32];
        float v0 = xl0 + xr0;  v0 = v0 > 0.f ? v0 : 0.2f * v0;
        float v1 = xl1v + xr1v; v1 = v1 > 0.f ? v1 : 0.2f * v1;
        float sc = v0 * at0 + v1 * at1;
        #pragma unroll
        for (int o = 16; o > 0; o >>= 1) sc += __shfl_xor_sync(0xffffffffu, sc, o);
        if (sc > m) {
            float r = __expf(m - sc);
            den *= r; acc0 *= r; acc1 *= r; m = sc;
        }
        float a = __expf(sc - m);
        den += a; acc0 += a * xl0; acc1 += a * xl1v;
    }

    float invd = 1.0f / den;
    float h0 = acc0 * invd + b2[l];      h0 = h0 > 0.f ? h0 : __expf(h0) - 1.f;
    float h1 = acc1 * invd + b2[l + 32]; h1 = h1 > 0.f ? h1 : __expf(h1) - 1.f;
    sh2[w][l] = h0; sh2[w][l + 32] = h1;
    __syncwarp();

    float o = sb[l];
    #pragma unroll
    for (int k = 0; k < 64; k++) o += sh2[w][k] * sW[k * 32 + l];
    out[(size_t)n * OUTF + l] = o > 0.f ? o : __expf(o) - 1.f;
}

// ---------------- launch ------------------------------------------------------
extern "C" void kernel_launch(void* const* d_in, const int* in_sizes, int n_in,
                              void* d_out, int out_size) {
    const float* x    = (const float*)d_in[0];
    const int*   ei   = (const int*)  d_in[1];
    const float* W1l  = (const float*)d_in[2];
    const float* W1r  = (const float*)d_in[3];
    const float* att1 = (const float*)d_in[4];
    const float* b1   = (const float*)d_in[5];
    const float* W2l  = (const float*)d_in[6];
    const float* W2r  = (const float*)d_in[7];
    const float* att2 = (const float*)d_in[8];
    const float* b2   = (const float*)d_in[9];
    const float* Wlin = (const float*)d_in[10];
    const float* blin = (const float*)d_in[11];
    float* out = (float*)d_out;

    float *p_xl1, *p_xr1, *p_xl2, *p_xr2;
    __nv_bfloat16 *p_xh, *p_xlo, *p_w1h, *p_w1lo, *p_h1h, *p_h1lo, *p_w2h, *p_w2lo;
    cudaGetSymbolAddress((void**)&p_xl1,  g_xl1);
    cudaGetSymbolAddress((void**)&p_xr1,  g_xr1);
    cudaGetSymbolAddress((void**)&p_xl2,  g_xl2);
    cudaGetSymbolAddress((void**)&p_xr2,  g_xr2);
    cudaGetSymbolAddress((void**)&p_xh,   g_xh);
    cudaGetSymbolAddress((void**)&p_xlo,  g_xlo);
    cudaGetSymbolAddress((void**)&p_w1h,  g_w1h);
    cudaGetSymbolAddress((void**)&p_w1lo, g_w1lo);
    cudaGetSymbolAddress((void**)&p_h1h,  g_h1h);
    cudaGetSymbolAddress((void**)&p_h1lo, g_h1lo);
    cudaGetSymbolAddress((void**)&p_w2h,  g_w2h);
    cudaGetSymbolAddress((void**)&p_w2lo, g_w2lo);

    // CSR build
    init_deg_kernel<<<(N_NODES + 255) / 256, 256>>>();
    count_kernel<<<(E_TOT + 255) / 256, 256>>>(ei);
    scan_kernel<<<1, 1024>>>();
    scatter_kernel<<<(E_TOT + 255) / 256, 256>>>(ei);

    // operand splits
    split_x_kernel <<<(N_NODES * D_IN + 255) / 256, 256>>>(x);
    split_w1_kernel<<<(F1 * D_IN + 255) / 256, 256>>>(W1l, W1r);
    split_w2_kernel<<<(F2 * F1 + 255) / 256, 256>>>(W2l, W2r);

    // Layer 1: xl1/xr1 = x @ W1{l,r}  (tensor pipe)
    gemm_mma<<<dim3(16, (N_NODES + 127) / 128), 256>>>(
        p_xh, p_xlo, p_w1h, p_w1lo, p_xl1, p_xr1, N_NODES, F1, D_IN, 8);
    gat1_kernel<<<N_NODES, 256>>>(ei, att1, b1);

    // Layer 2: xl2/xr2 = h1 @ W2{l,r}  (tensor pipe)
    gemm_mma<<<dim3(2, (N_NODES + 127) / 128), 256>>>(
        p_h1h, p_h1lo, p_w2h, p_w2lo, p_xl2, p_xr2, N_NODES, F2, F1, 1);
    gat2_kernel<<<N_NODES / 8, 256>>>(ei, att2, b2, Wlin, blin, out);
}

// round 7
// speedup vs baseline: 2.0389x; 1.1723x over previous
#include <cuda_runtime.h>
#include <cuda_bf16.h>
#include <math.h>
#include <stdint.h>

#define N_NODES 20000
#define D_IN    128
#define E_RAW   320000
#define E_TOT   (E_RAW + N_NODES)
#define F1      512
#define F2      64
#define OUTF    32

// ---------------- scratch ----------------------------------------------------
__device__ float g_xl1[(size_t)N_NODES * F1];
__device__ float g_xr1[(size_t)N_NODES * F1];
__device__ float g_xl2[(size_t)N_NODES * F2];
__device__ float g_xr2[(size_t)N_NODES * F2];
__device__ int   g_deg[N_NODES];
__device__ int   g_part[N_NODES];
__device__ int   g_bsum[32];
__device__ int   g_boff[32];
__device__ int   g_rowptr[N_NODES + 1];
__device__ int   g_cursor[N_NODES];
__device__ int   g_eidx[E_TOT];
// split-bf16 operands
__device__ __nv_bfloat16 g_xh  [(size_t)N_NODES * D_IN];
__device__ __nv_bfloat16 g_xlo [(size_t)N_NODES * D_IN];
__device__ __nv_bfloat16 g_h1h [(size_t)N_NODES * F1];
__device__ __nv_bfloat16 g_h1lo[(size_t)N_NODES * F1];
__device__ __nv_bfloat16 g_w1h [2 * F1 * D_IN];   // [w][n][k]
__device__ __nv_bfloat16 g_w1lo[2 * F1 * D_IN];
__device__ __nv_bfloat16 g_w2h [2 * F2 * F1];     // [w][n][k]
__device__ __nv_bfloat16 g_w2lo[2 * F2 * F1];

__device__ __forceinline__ int e_dst(const int* ei, int e) {
    return (e < E_RAW) ? ei[E_RAW + e] : (e - E_RAW);
}

// ---------------- CSR build --------------------------------------------------
__global__ void count_kernel(const int* __restrict__ ei) {
    int e = blockIdx.x * blockDim.x + threadIdx.x;
    if (e >= E_TOT) return;
    atomicAdd(&g_deg[e_dst(ei, e)], 1);
}

// phase 1: per-block inclusive scan of deg (1024/block)
__global__ void scan1_kernel() {
    __shared__ int sh[1024];
    int t = threadIdx.x;
    int i = blockIdx.x * 1024 + t;
    int v = (i < N_NODES) ? g_deg[i] : 0;
    sh[t] = v;
    __syncthreads();
    #pragma unroll
    for (int off = 1; off < 1024; off <<= 1) {
        int u = (t >= off) ? sh[t - off] : 0;
        __syncthreads();
        sh[t] += u;
        __syncthreads();
    }
    if (i < N_NODES) g_part[i] = sh[t];
    if (t == 1023) g_bsum[blockIdx.x] = sh[t];
}
// phase 2: exclusive scan of block sums (1 warp)
__global__ void scan2_kernel(int nblk) {
    int t = threadIdx.x;
    int v = (t < nblk) ? g_bsum[t] : 0;
    int incl = v;
    #pragma unroll
    for (int off = 1; off < 32; off <<= 1) {
        int u = __shfl_up_sync(0xffffffffu, incl, off);
        if (t >= off) incl += u;
    }
    if (t < nblk) g_boff[t] = incl - v;
}
// phase 3: add offsets -> rowptr/cursor
__global__ void scan3_kernel() {
    int i = blockIdx.x * blockDim.x + threadIdx.x;
    if (i >= N_NODES) return;
    int boff = g_boff[i >> 10];
    int rp = g_part[i] - g_deg[i] + boff;
    g_rowptr[i] = rp;
    g_cursor[i] = rp;
    if (i == N_NODES - 1) g_rowptr[N_NODES] = g_part[i] + boff;
}

__global__ void scatter_kernel(const int* __restrict__ ei) {
    int e = blockIdx.x * blockDim.x + threadIdx.x;
    if (e >= E_TOT) return;
    int d = e_dst(ei, e);
    int pos = atomicAdd(&g_cursor[d], 1);
    g_eidx[pos] = e;
}

// ---------------- fp32 -> split bf16 (hi + lo) --------------------------------
__device__ __forceinline__ void split2(float v, __nv_bfloat16* ph, __nv_bfloat16* pl) {
    __nv_bfloat16 h = __float2bfloat16(v);
    *ph = h;
    *pl = __float2bfloat16(v - __bfloat162float(h));
}
__global__ void split_x_kernel(const float* __restrict__ x) {
    int i = blockIdx.x * blockDim.x + threadIdx.x;
    if (i >= N_NODES * D_IN) return;
    split2(x[i], &g_xh[i], &g_xlo[i]);
}
// merged weight split: W1 [128,512]->[n][k], W2 [512,64]->[n][k]
__global__ void split_w_kernel(const float* __restrict__ W1l, const float* __restrict__ W1r,
                               const float* __restrict__ W2l, const float* __restrict__ W2r) {
    int i = blockIdx.x * blockDim.x + threadIdx.x;
    if (i < F1 * D_IN) {
        int k = i / F1, n = i % F1;
        split2(W1l[i], &g_w1h[n * D_IN + k], &g_w1lo[n * D_IN + k]);
        split2(W1r[i], &g_w1h[F1 * D_IN + n * D_IN + k], &g_w1lo[F1 * D_IN + n * D_IN + k]);
    } else {
        int j = i - F1 * D_IN;
        if (j >= F2 * F1) return;
        int k = j / F2, n = j % F2;
        split2(W2l[j], &g_w2h[n * F1 + k], &g_w2lo[n * F1 + k]);
        split2(W2r[j], &g_w2h[F2 * F1 + n * F1 + k], &g_w2lo[F2 * F1 + n * F1 + k]);
    }
}

// ---------------- split-bf16 GEMM on mma.sync (HMMA) --------------------------
#define SPAD 40

__device__ __forceinline__ uint32_t lds_u32(const __nv_bfloat16* s, int row, int col) {
    return *(const uint32_t*)((const char*)s + row * (SPAD * 2) + col * 2);
}
__device__ __forceinline__ void mma_bf16(float* c, const uint32_t* a, const uint32_t* b) {
    asm volatile(
        "mma.sync.aligned.m16n8k16.row.col.f32.bf16.bf16.f32 "
        "{%0,%1,%2,%3}, {%4,%5,%6,%7}, {%8,%9}, {%0,%1,%2,%3};"
        : "+f"(c[0]), "+f"(c[1]), "+f"(c[2]), "+f"(c[3])
        : "r"(a[0]), "r"(a[1]), "r"(a[2]), "r"(a[3]), "r"(b[0]), "r"(b[1]));
}

__global__ void __launch_bounds__(256) gemm_mma(
    const __nv_bfloat16* __restrict__ Ah, const __nv_bfloat16* __restrict__ Al,
    const __nv_bfloat16* __restrict__ Bh, const __nv_bfloat16* __restrict__ Bl,
    float* __restrict__ C0, float* __restrict__ C1,
    int M, int N, int K, int ntPerW)
{
    __shared__ __nv_bfloat16 sAh[128 * SPAD], sAl[128 * SPAD];
    __shared__ __nv_bfloat16 sBh[64 * SPAD],  sBl[64 * SPAD];

    int tid = threadIdx.x;
    int wid = tid >> 5, lane = tid & 31;
    int w  = blockIdx.x / ntPerW;
    int nt = blockIdx.x % ntPerW;
    int bm = blockIdx.y * 128;

    const __nv_bfloat16* Bth = Bh + (size_t)w * N * K + (size_t)(nt * 64) * K;
    const __nv_bfloat16* Btl = Bl + (size_t)w * N * K + (size_t)(nt * 64) * K;
    float* C = w ? C1 : C0;

    int wm = wid & 3, wn = wid >> 2;
    int g = lane >> 2, t2 = (lane & 3) * 2;

    float acc[2][4][4];
    #pragma unroll
    for (int i = 0; i < 2; i++)
        #pragma unroll
        for (int j = 0; j < 4; j++)
            #pragma unroll
            for (int q = 0; q < 4; q++) acc[i][j][q] = 0.f;

    int nk = K >> 5;
    for (int kt = 0; kt < nk; kt++) {
        int k0 = kt << 5;
        #pragma unroll
        for (int p = 0; p < 2; p++) {
            int idx = tid + p * 256;
            int r = idx >> 2, q = idx & 3;
            int gm = bm + r;
            uint4 vh = make_uint4(0, 0, 0, 0), vl = vh;
            if (gm < M) {
                vh = *(const uint4*)(Ah + (size_t)gm * K + k0 + q * 8);
                vl = *(const uint4*)(Al + (size_t)gm * K + k0 + q * 8);
            }
            *(uint4*)((char*)sAh + r * (SPAD * 2) + q * 16) = vh;
            *(uint4*)((char*)sAl + r * (SPAD * 2) + q * 16) = vl;
        }
        {
            int r = tid >> 2, q = tid & 3;
            *(uint4*)((char*)sBh + r * (SPAD * 2) + q * 16) =
                *(const uint4*)(Bth + (size_t)r * K + k0 + q * 8);
            *(uint4*)((char*)sBl + r * (SPAD * 2) + q * 16) =
                *(const uint4*)(Btl + (size_t)r * K + k0 + q * 8);
        }
        __syncthreads();

        #pragma unroll
        for (int kk = 0; kk < 32; kk += 16) {
            uint32_t ah[2][4], al[2][4], bhf[4][2], blf[4][2];
            #pragma unroll
            for (int i = 0; i < 2; i++) {
                int r = wm * 32 + i * 16;
                ah[i][0] = lds_u32(sAh, r + g,     kk + t2);
                ah[i][1] = lds_u32(sAh, r + g + 8, kk + t2);
                ah[i][2] = lds_u32(sAh, r + g,     kk + t2 + 8);
                ah[i][3] = lds_u32(sAh, r + g + 8, kk + t2 + 8);
                al[i][0] = lds_u32(sAl, r + g,     kk + t2);
                al[i][1] = lds_u32(sAl, r + g + 8, kk + t2);
                al[i][2] = lds_u32(sAl, r + g,     kk + t2 + 8);
                al[i][3] = lds_u32(sAl, r + g + 8, kk + t2 + 8);
            }
            #pragma unroll
            for (int j = 0; j < 4; j++) {
                int n = wn * 32 + j * 8 + g;
                bhf[j][0] = lds_u32(sBh, n, kk + t2);
                bhf[j][1] = lds_u32(sBh, n, kk + t2 + 8);
                blf[j][0] = lds_u32(sBl, n, kk + t2);
                blf[j][1] = lds_u32(sBl, n, kk + t2 + 8);
            }
            #pragma unroll
            for (int i = 0; i < 2; i++)
                #pragma unroll
                for (int j = 0; j < 4; j++) {
                    mma_bf16(acc[i][j], ah[i], bhf[j]);
                    mma_bf16(acc[i][j], ah[i], blf[j]);
                    mma_bf16(acc[i][j], al[i], bhf[j]);
                }
        }
        __syncthreads();
    }

    #pragma unroll
    for (int i = 0; i < 2; i++) {
        int r0 = bm + wm * 32 + i * 16 + g;
        #pragma unroll
        for (int j = 0; j < 4; j++) {
            int c = nt * 64 + wn * 32 + j * 8 + t2;
            if (r0 < M)
                *(float2*)(C + (size_t)r0 * N + c) = make_float2(acc[i][j][0], acc[i][j][1]);
            if (r0 + 8 < M)
                *(float2*)(C + (size_t)(r0 + 8) * N + c) = make_float2(acc[i][j][2], acc[i][j][3]);
        }
    }
}

// ---------------- fused GAT layer 1 (block/node, warp/head, dual-edge) --------
// 16 lanes x float4 cover 64 channels of one head. Lanes 0-15 process even
// CSR slots, 16-31 odd. Both halves run ceil(deg/2) iterations (predicated
// tail) so in-loop full-warp shuffles stay convergent.
__global__ void gat1_kernel(const int* __restrict__ ei, const float* __restrict__ att,
                            const float* __restrict__ b1)
{
    int n = blockIdx.x;
    int w = threadIdx.x >> 5, l = threadIdx.x & 31;
    int half = l >> 4, hl = l & 15;
    int c = w * 64 + hl * 4;

    float4 xr = *(const float4*)(g_xr1 + (size_t)n * F1 + c);
    float4 at = *(const float4*)(att + c);

    int r0 = g_rowptr[n], r1 = g_rowptr[n + 1];
    int nIter = (r1 - r0 + 1) >> 1;
    float m = -INFINITY, den = 0.f;
    float4 acc = make_float4(0.f, 0.f, 0.f, 0.f);

    for (int it = 0; it < nIter; it++) {
        int p = r0 + it * 2 + half;
        bool valid = p < r1;
        int pp = valid ? p : (r1 - 1);
        int e = g_eidx[pp];
        int s = (e < E_RAW) ? ei[e] : (e - E_RAW);
        float4 xl = *(const float4*)(g_xl1 + (size_t)s * F1 + c);
        float v0 = xl.x + xr.x; v0 = v0 > 0.f ? v0 : 0.2f * v0;
        float v1 = xl.y + xr.y; v1 = v1 > 0.f ? v1 : 0.2f * v1;
        float v2 = xl.z + xr.z; v2 = v2 > 0.f ? v2 : 0.2f * v2;
        float v3 = xl.w + xr.w; v3 = v3 > 0.f ? v3 : 0.2f * v3;
        float sc = v0 * at.x + v1 * at.y + v2 * at.z + v3 * at.w;
        sc += __shfl_xor_sync(0xffffffffu, sc, 1);
        sc += __shfl_xor_sync(0xffffffffu, sc, 2);
        sc += __shfl_xor_sync(0xffffffffu, sc, 4);
        sc += __shfl_xor_sync(0xffffffffu, sc, 8);
        if (valid && sc > m) {
            float r = __expf(m - sc);
            den *= r; acc.x *= r; acc.y *= r; acc.z *= r; acc.w *= r; m = sc;
        }
        float a = valid ? __expf(sc - m) : 0.f;
        den += a;
        acc.x += a * xl.x; acc.y += a * xl.y; acc.z += a * xl.z; acc.w += a * xl.w;
    }

    // merge the two half-warp softmax states (half 0 always has >=1 valid edge)
    float mo   = __shfl_xor_sync(0xffffffffu, m, 16);
    float deno = __shfl_xor_sync(0xffffffffu, den, 16);
    float4 ao;
    ao.x = __shfl_xor_sync(0xffffffffu, acc.x, 16);
    ao.y = __shfl_xor_sync(0xffffffffu, acc.y, 16);
    ao.z = __shfl_xor_sync(0xffffffffu, acc.z, 16);
    ao.w = __shfl_xor_sync(0xffffffffu, acc.w, 16);
    float M = fmaxf(m, mo);
    float sA = (m  > -INFINITY) ? __expf(m  - M) : 0.f;
    float sB = (mo > -INFINITY) ? __expf(mo - M) : 0.f;
    den = den * sA + deno * sB;
    acc.x = acc.x * sA + ao.x * sB;
    acc.y = acc.y * sA + ao.y * sB;
    acc.z = acc.z * sA + ao.z * sB;
    acc.w = acc.w * sA + ao.w * sB;

    if (half == 0) {
        float4 bb = *(const float4*)(b1 + c);
        float invd = 1.0f / den;
        float o0 = acc.x * invd + bb.x; o0 = o0 > 0.f ? o0 : __expf(o0) - 1.f;
        float o1 = acc.y * invd + bb.y; o1 = o1 > 0.f ? o1 : __expf(o1) - 1.f;
        float o2 = acc.z * invd + bb.z; o2 = o2 > 0.f ? o2 : __expf(o2) - 1.f;
        float o3 = acc.w * invd + bb.w; o3 = o3 > 0.f ? o3 : __expf(o3) - 1.f;
        __nv_bfloat16 h[4], lo[4];
        split2(o0, &h[0], &lo[0]); split2(o1, &h[1], &lo[1]);
        split2(o2, &h[2], &lo[2]); split2(o3, &h[3], &lo[3]);
        *(uint2*)(g_h1h  + (size_t)n * F1 + c) = *(const uint2*)h;
        *(uint2*)(g_h1lo + (size_t)n * F1 + c) = *(const uint2*)lo;
    }
}

// ---------------- fused GAT layer 2 + linear + elu (dual-edge) ----------------
__global__ void gat2_kernel(const int* __restrict__ ei, const float* __restrict__ att,
                            const float* __restrict__ b2,
                            const float* __restrict__ Wlin, const float* __restrict__ blin,
                            float* __restrict__ out)
{
    __shared__ float sW[64 * 32];
    __shared__ float sb[32];
    __shared__ float sh2[8][64];
    for (int i = threadIdx.x; i < 64 * 32; i += 256) sW[i] = Wlin[i];
    if (threadIdx.x < 32) sb[threadIdx.x] = blin[threadIdx.x];
    __syncthreads();

    int w = threadIdx.x >> 5, l = threadIdx.x & 31;
    int half = l >> 4, hl = l & 15;
    int n = blockIdx.x * 8 + w;
    int c = hl * 4;

    float4 xr = *(const float4*)(g_xr2 + (size_t)n * F2 + c);
    float4 at = *(const float4*)(att + c);

    int r0 = g_rowptr[n], r1 = g_rowptr[n + 1];
    int nIter = (r1 - r0 + 1) >> 1;
    float m = -INFINITY, den = 0.f;
    float4 acc = make_float4(0.f, 0.f, 0.f, 0.f);

    for (int it = 0; it < nIter; it++) {
        int p = r0 + it * 2 + half;
        bool valid = p < r1;
        int pp = valid ? p : (r1 - 1);
        int e = g_eidx[pp];
        int s = (e < E_RAW) ? ei[e] : (e - E_RAW);
        float4 xl = *(const float4*)(g_xl2 + (size_t)s * F2 + c);
        float v0 = xl.x + xr.x; v0 = v0 > 0.f ? v0 : 0.2f * v0;
        float v1 = xl.y + xr.y; v1 = v1 > 0.f ? v1 : 0.2f * v1;
        float v2 = xl.z + xr.z; v2 = v2 > 0.f ? v2 : 0.2f * v2;
        float v3 = xl.w + xr.w; v3 = v3 > 0.f ? v3 : 0.2f * v3;
        float sc = v0 * at.x + v1 * at.y + v2 * at.z + v3 * at.w;
        sc += __shfl_xor_sync(0xffffffffu, sc, 1);
        sc += __shfl_xor_sync(0xffffffffu, sc, 2);
        sc += __shfl_xor_sync(0xffffffffu, sc, 4);
        sc += __shfl_xor_sync(0xffffffffu, sc, 8);
        if (valid && sc > m) {
            float r = __expf(m - sc);
            den *= r; acc.x *= r; acc.y *= r; acc.z *= r; acc.w *= r; m = sc;
        }
        float a = valid ? __expf(sc - m) : 0.f;
        den += a;
        acc.x += a * xl.x; acc.y += a * xl.y; acc.z += a * xl.z; acc.w += a * xl.w;
    }

    float mo   = __shfl_xor_sync(0xffffffffu, m, 16);
    float deno = __shfl_xor_sync(0xffffffffu, den, 16);
    float4 ao;
    ao.x = __shfl_xor_sync(0xffffffffu, acc.x, 16);
    ao.y = __shfl_xor_sync(0xffffffffu, acc.y, 16);
    ao.z = __shfl_xor_sync(0xffffffffu, acc.z, 16);
    ao.w = __shfl_xor_sync(0xffffffffu, acc.w, 16);
    float M = fmaxf(m, mo);
    float sA = (m  > -INFINITY) ? __expf(m  - M) : 0.f;
    float sB = (mo > -INFINITY) ? __expf(mo - M) : 0.f;
    den = den * sA + deno * sB;
    acc.x = acc.x * sA + ao.x * sB;
    acc.y = acc.y * sA + ao.y * sB;
    acc.z = acc.z * sA + ao.z * sB;
    acc.w = acc.w * sA + ao.w * sB;

    if (half == 0) {
        float4 bb = *(const float4*)(b2 + c);
        float invd = 1.0f / den;
        float h0 = acc.x * invd + bb.x; h0 = h0 > 0.f ? h0 : __expf(h0) - 1.f;
        float h1 = acc.y * invd + bb.y; h1 = h1 > 0.f ? h1 : __expf(h1) - 1.f;
        float h2 = acc.z * invd + bb.z; h2 = h2 > 0.f ? h2 : __expf(h2) - 1.f;
        float h3 = acc.w * invd + bb.w; h3 = h3 > 0.f ? h3 : __expf(h3) - 1.f;
        sh2[w][c] = h0; sh2[w][c + 1] = h1; sh2[w][c + 2] = h2; sh2[w][c + 3] = h3;
    }
    __syncwarp();

    float o = sb[l];
    #pragma unroll
    for (int k = 0; k < 64; k++) o += sh2[w][k] * sW[k * 32 + l];
    out[(size_t)n * OUTF + l] = o > 0.f ? o : __expf(o) - 1.f;
}

// ---------------- launch ------------------------------------------------------
extern "C" void kernel_launch(void* const* d_in, const int* in_sizes, int n_in,
                              void* d_out, int out_size) {
    const float* x    = (const float*)d_in[0];
    const int*   ei   = (const int*)  d_in[1];
    const float* W1l  = (const float*)d_in[2];
    const float* W1r  = (const float*)d_in[3];
    const float* att1 = (const float*)d_in[4];
    const float* b1   = (const float*)d_in[5];
    const float* W2l  = (const float*)d_in[6];
    const float* W2r  = (const float*)d_in[7];
    const float* att2 = (const float*)d_in[8];
    const float* b2   = (const float*)d_in[9];
    const float* Wlin = (const float*)d_in[10];
    const float* blin = (const float*)d_in[11];
    float* out = (float*)d_out;

    float *p_xl1, *p_xr1, *p_xl2, *p_xr2;
    int* p_deg;
    __nv_bfloat16 *p_xh, *p_xlo, *p_w1h, *p_w1lo, *p_h1h, *p_h1lo, *p_w2h, *p_w2lo;
    cudaGetSymbolAddress((void**)&p_xl1,  g_xl1);
    cudaGetSymbolAddress((void**)&p_xr1,  g_xr1);
    cudaGetSymbolAddress((void**)&p_xl2,  g_xl2);
    cudaGetSymbolAddress((void**)&p_xr2,  g_xr2);
    cudaGetSymbolAddress((void**)&p_deg,  g_deg);
    cudaGetSymbolAddress((void**)&p_xh,   g_xh);
    cudaGetSymbolAddress((void**)&p_xlo,  g_xlo);
    cudaGetSymbolAddress((void**)&p_w1h,  g_w1h);
    cudaGetSymbolAddress((void**)&p_w1lo, g_w1lo);
    cudaGetSymbolAddress((void**)&p_h1h,  g_h1h);
    cudaGetSymbolAddress((void**)&p_h1lo, g_h1lo);
    cudaGetSymbolAddress((void**)&p_w2h,  g_w2h);
    cudaGetSymbolAddress((void**)&p_w2lo, g_w2lo);

    // CSR build
    cudaMemsetAsync(p_deg, 0, N_NODES * sizeof(int));
    count_kernel<<<(E_TOT + 255) / 256, 256>>>(ei);
    int nblk = (N_NODES + 1023) / 1024;
    scan1_kernel<<<nblk, 1024>>>();
    scan2_kernel<<<1, 32>>>(nblk);
    scan3_kernel<<<(N_NODES + 255) / 256, 256>>>();
    scatter_kernel<<<(E_TOT + 255) / 256, 256>>>(ei);

    // operand splits
    split_x_kernel<<<(N_NODES * D_IN + 255) / 256, 256>>>(x);
    split_w_kernel<<<(F1 * D_IN + F2 * F1 + 255) / 256, 256>>>(W1l, W1r, W2l, W2r);

    // Layer 1: xl1/xr1 = x @ W1{l,r}
    gemm_mma<<<dim3(16, (N_NODES + 127) / 128), 256>>>(
        p_xh, p_xlo, p_w1h, p_w1lo, p_xl1, p_xr1, N_NODES, F1, D_IN, 8);
    gat1_kernel<<<N_NODES, 256>>>(ei, att1, b1);

    // Layer 2: xl2/xr2 = h1 @ W2{l,r}
    gemm_mma<<<dim3(2, (N_NODES + 127) / 128), 256>>>(
        p_h1h, p_h1lo, p_w2h, p_w2lo, p_xl2, p_xr2, N_NODES, F2, F1, 1);
    gat2_kernel<<<N_NODES / 8, 256>>>(ei, att2, b2, Wlin, blin, out);
}

// round 8
// speedup vs baseline: 2.1534x; 1.0562x over previous
#include <cuda_runtime.h>
#include <cuda_bf16.h>
#include <math.h>
#include <stdint.h>

#define N_NODES 20000
#define D_IN    128
#define E_RAW   320000
#define E_TOT   (E_RAW + N_NODES)
#define F1      512
#define F2      64
#define OUTF    32

// ---------------- scratch ----------------------------------------------------
__device__ float g_xl1[(size_t)N_NODES * F1];
__device__ float g_xr1[(size_t)N_NODES * F1];
__device__ float g_xl2[(size_t)N_NODES * F2];
__device__ float g_xr2[(size_t)N_NODES * F2];
__device__ int   g_deg[N_NODES];
__device__ int   g_part[N_NODES];
__device__ int   g_bsum[32];
__device__ int   g_rowptr[N_NODES + 1];
__device__ int   g_cursor[N_NODES];
__device__ int   g_eidx[E_TOT];
// split-bf16 operands
__device__ __nv_bfloat16 g_xh  [(size_t)N_NODES * D_IN];
__device__ __nv_bfloat16 g_xlo [(size_t)N_NODES * D_IN];
__device__ __nv_bfloat16 g_h1h [(size_t)N_NODES * F1];
__device__ __nv_bfloat16 g_h1lo[(size_t)N_NODES * F1];
__device__ __nv_bfloat16 g_w1h [2 * F1 * D_IN];   // [w][n][k]
__device__ __nv_bfloat16 g_w1lo[2 * F1 * D_IN];
__device__ __nv_bfloat16 g_w2h [2 * F2 * F1];     // [w][n][k]
__device__ __nv_bfloat16 g_w2lo[2 * F2 * F1];

__device__ __forceinline__ int e_dst(const int* ei, int e) {
    return (e < E_RAW) ? ei[E_RAW + e] : (e - E_RAW);
}

// ---------------- CSR build --------------------------------------------------
__global__ void count_kernel(const int* __restrict__ ei) {
    int e = blockIdx.x * blockDim.x + threadIdx.x;
    if (e >= E_TOT) return;
    atomicAdd(&g_deg[e_dst(ei, e)], 1);
}

// phase 1: per-block inclusive scan of deg (1024/block)
__global__ void scan1_kernel() {
    __shared__ int sh[1024];
    int t = threadIdx.x;
    int i = blockIdx.x * 1024 + t;
    int v = (i < N_NODES) ? g_deg[i] : 0;
    sh[t] = v;
    __syncthreads();
    #pragma unroll
    for (int off = 1; off < 1024; off <<= 1) {
        int u = (t >= off) ? sh[t - off] : 0;
        __syncthreads();
        sh[t] += u;
        __syncthreads();
    }
    if (i < N_NODES) g_part[i] = sh[t];
    if (t == 1023) g_bsum[blockIdx.x] = sh[t];
}
// phase 2+3 folded: each thread sums preceding block sums (<=19 cached loads)
__global__ void scan23_kernel() {
    int i = blockIdx.x * blockDim.x + threadIdx.x;
    if (i >= N_NODES) return;
    int b = i >> 10;
    int boff = 0;
    for (int j = 0; j < b; j++) boff += g_bsum[j];
    int rp = g_part[i] - g_deg[i] + boff;
    g_rowptr[i] = rp;
    g_cursor[i] = rp;
    if (i == N_NODES - 1) g_rowptr[N_NODES] = g_part[i] + boff;
}

__global__ void scatter_kernel(const int* __restrict__ ei) {
    int e = blockIdx.x * blockDim.x + threadIdx.x;
    if (e >= E_TOT) return;
    int d = e_dst(ei, e);
    int pos = atomicAdd(&g_cursor[d], 1);
    g_eidx[pos] = e;
}

// ---------------- fp32 -> split bf16 (hi + lo) --------------------------------
__device__ __forceinline__ void split2(float v, __nv_bfloat16* ph, __nv_bfloat16* pl) {
    __nv_bfloat16 h = __float2bfloat16(v);
    *ph = h;
    *pl = __float2bfloat16(v - __bfloat162float(h));
}
__global__ void split_x_kernel(const float* __restrict__ x) {
    int i = blockIdx.x * blockDim.x + threadIdx.x;
    if (i >= N_NODES * D_IN) return;
    split2(x[i], &g_xh[i], &g_xlo[i]);
}
// merged weight split: W1 [128,512]->[n][k], W2 [512,64]->[n][k]
__global__ void split_w_kernel(const float* __restrict__ W1l, const float* __restrict__ W1r,
                               const float* __restrict__ W2l, const float* __restrict__ W2r) {
    int i = blockIdx.x * blockDim.x + threadIdx.x;
    if (i < F1 * D_IN) {
        int k = i / F1, n = i % F1;
        split2(W1l[i], &g_w1h[n * D_IN + k], &g_w1lo[n * D_IN + k]);
        split2(W1r[i], &g_w1h[F1 * D_IN + n * D_IN + k], &g_w1lo[F1 * D_IN + n * D_IN + k]);
    } else {
        int j = i - F1 * D_IN;
        if (j >= F2 * F1) return;
        int k = j / F2, n = j % F2;
        split2(W2l[j], &g_w2h[n * F1 + k], &g_w2lo[n * F1 + k]);
        split2(W2r[j], &g_w2h[F2 * F1 + n * F1 + k], &g_w2lo[F2 * F1 + n * F1 + k]);
    }
}

// ---------------- split-bf16 GEMM on mma.sync (HMMA), reg-prefetch ------------
#define SPAD 40

__device__ __forceinline__ uint32_t lds_u32(const __nv_bfloat16* s, int row, int col) {
    return *(const uint32_t*)((const char*)s + row * (SPAD * 2) + col * 2);
}
__device__ __forceinline__ void mma_bf16(float* c, const uint32_t* a, const uint32_t* b) {
    asm volatile(
        "mma.sync.aligned.m16n8k16.row.col.f32.bf16.bf16.f32 "
        "{%0,%1,%2,%3}, {%4,%5,%6,%7}, {%8,%9}, {%0,%1,%2,%3};"
        : "+f"(c[0]), "+f"(c[1]), "+f"(c[2]), "+f"(c[3])
        : "r"(a[0]), "r"(a[1]), "r"(a[2]), "r"(a[3]), "r"(b[0]), "r"(b[1]));
}

__global__ void __launch_bounds__(256) gemm_mma(
    const __nv_bfloat16* __restrict__ Ah, const __nv_bfloat16* __restrict__ Al,
    const __nv_bfloat16* __restrict__ Bh, const __nv_bfloat16* __restrict__ Bl,
    float* __restrict__ C0, float* __restrict__ C1,
    int M, int N, int K, int ntPerW)
{
    __shared__ __nv_bfloat16 sAh[128 * SPAD], sAl[128 * SPAD];
    __shared__ __nv_bfloat16 sBh[64 * SPAD],  sBl[64 * SPAD];

    int tid = threadIdx.x;
    int wid = tid >> 5, lane = tid & 31;
    int w  = blockIdx.x / ntPerW;
    int nt = blockIdx.x % ntPerW;
    int bm = blockIdx.y * 128;

    const __nv_bfloat16* Bth = Bh + (size_t)w * N * K + (size_t)(nt * 64) * K;
    const __nv_bfloat16* Btl = Bl + (size_t)w * N * K + (size_t)(nt * 64) * K;
    float* C = w ? C1 : C0;

    int wm = wid & 3, wn = wid >> 2;
    int g = lane >> 2, t2 = (lane & 3) * 2;

    // staging coords
    int ra0 = tid >> 2, qa0 = tid & 3;                 // A row/quads (p=0)
    int ra1 = (tid + 256) >> 2, qa1 = (tid + 256) & 3; // A row/quads (p=1)
    int rb = tid >> 2, qb = tid & 3;                   // B

    float acc[2][4][4];
    #pragma unroll
    for (int i = 0; i < 2; i++)
        #pragma unroll
        for (int j = 0; j < 4; j++)
            #pragma unroll
            for (int q = 0; q < 4; q++) acc[i][j][q] = 0.f;

    int nk = K >> 5;
    uint4 pavh0, pavl0, pavh1, pavl1, pbvh, pbvl;
    // prologue loads (k0 = 0)
    {
        int gm0 = bm + ra0, gm1 = bm + ra1;
        pavh0 = pavl0 = make_uint4(0,0,0,0);
        pavh1 = pavl1 = make_uint4(0,0,0,0);
        if (gm0 < M) { pavh0 = *(const uint4*)(Ah + (size_t)gm0 * K + qa0 * 8);
                       pavl0 = *(const uint4*)(Al + (size_t)gm0 * K + qa0 * 8); }
        if (gm1 < M) { pavh1 = *(const uint4*)(Ah + (size_t)gm1 * K + qa1 * 8);
                       pavl1 = *(const uint4*)(Al + (size_t)gm1 * K + qa1 * 8); }
        pbvh = *(const uint4*)(Bth + (size_t)rb * K + qb * 8);
        pbvl = *(const uint4*)(Btl + (size_t)rb * K + qb * 8);
    }

    for (int kt = 0; kt < nk; kt++) {
        *(uint4*)((char*)sAh + ra0 * (SPAD * 2) + qa0 * 16) = pavh0;
        *(uint4*)((char*)sAl + ra0 * (SPAD * 2) + qa0 * 16) = pavl0;
        *(uint4*)((char*)sAh + ra1 * (SPAD * 2) + qa1 * 16) = pavh1;
        *(uint4*)((char*)sAl + ra1 * (SPAD * 2) + qa1 * 16) = pavl1;
        *(uint4*)((char*)sBh + rb * (SPAD * 2) + qb * 16) = pbvh;
        *(uint4*)((char*)sBl + rb * (SPAD * 2) + qb * 16) = pbvl;
        __syncthreads();

        if (kt + 1 < nk) {
            int k0 = (kt + 1) << 5;
            int gm0 = bm + ra0, gm1 = bm + ra1;
            if (gm0 < M) { pavh0 = *(const uint4*)(Ah + (size_t)gm0 * K + k0 + qa0 * 8);
                           pavl0 = *(const uint4*)(Al + (size_t)gm0 * K + k0 + qa0 * 8); }
            if (gm1 < M) { pavh1 = *(const uint4*)(Ah + (size_t)gm1 * K + k0 + qa1 * 8);
                           pavl1 = *(const uint4*)(Al + (size_t)gm1 * K + k0 + qa1 * 8); }
            pbvh = *(const uint4*)(Bth + (size_t)rb * K + k0 + qb * 8);
            pbvl = *(const uint4*)(Btl + (size_t)rb * K + k0 + qb * 8);
        }

        #pragma unroll
        for (int kk = 0; kk < 32; kk += 16) {
            uint32_t ah[2][4], al[2][4], bhf[4][2], blf[4][2];
            #pragma unroll
            for (int i = 0; i < 2; i++) {
                int r = wm * 32 + i * 16;
                ah[i][0] = lds_u32(sAh, r + g,     kk + t2);
                ah[i][1] = lds_u32(sAh, r + g + 8, kk + t2);
                ah[i][2] = lds_u32(sAh, r + g,     kk + t2 + 8);
                ah[i][3] = lds_u32(sAh, r + g + 8, kk + t2 + 8);
                al[i][0] = lds_u32(sAl, r + g,     kk + t2);
                al[i][1] = lds_u32(sAl, r + g + 8, kk + t2);
                al[i][2] = lds_u32(sAl, r + g,     kk + t2 + 8);
                al[i][3] = lds_u32(sAl, r + g + 8, kk + t2 + 8);
            }
            #pragma unroll
            for (int j = 0; j < 4; j++) {
                int n = wn * 32 + j * 8 + g;
                bhf[j][0] = lds_u32(sBh, n, kk + t2);
                bhf[j][1] = lds_u32(sBh, n, kk + t2 + 8);
                blf[j][0] = lds_u32(sBl, n, kk + t2);
                blf[j][1] = lds_u32(sBl, n, kk + t2 + 8);
            }
            #pragma unroll
            for (int i = 0; i < 2; i++)
                #pragma unroll
                for (int j = 0; j < 4; j++) {
                    mma_bf16(acc[i][j], ah[i], bhf[j]);
                    mma_bf16(acc[i][j], ah[i], blf[j]);
                    mma_bf16(acc[i][j], al[i], bhf[j]);
                }
        }
        __syncthreads();
    }

    #pragma unroll
    for (int i = 0; i < 2; i++) {
        int r0 = bm + wm * 32 + i * 16 + g;
        #pragma unroll
        for (int j = 0; j < 4; j++) {
            int c = nt * 64 + wn * 32 + j * 8 + t2;
            if (r0 < M)
                *(float2*)(C + (size_t)r0 * N + c) = make_float2(acc[i][j][0], acc[i][j][1]);
            if (r0 + 8 < M)
                *(float2*)(C + (size_t)(r0 + 8) * N + c) = make_float2(acc[i][j][2], acc[i][j][3]);
        }
    }
}

// ---------------- fused GAT layer 1 (block/node, warp/head, dual-edge) --------
__global__ void gat1_kernel(const int* __restrict__ ei, const float* __restrict__ att,
                            const float* __restrict__ b1)
{
    int n = blockIdx.x;
    int w = threadIdx.x >> 5, l = threadIdx.x & 31;
    int half = l >> 4, hl = l & 15;
    int c = w * 64 + hl * 4;

    float4 xr = *(const float4*)(g_xr1 + (size_t)n * F1 + c);
    float4 at = *(const float4*)(att + c);

    int r0 = g_rowptr[n], r1 = g_rowptr[n + 1];
    int nIter = (r1 - r0 + 1) >> 1;
    float m = -INFINITY, den = 0.f;
    float4 acc = make_float4(0.f, 0.f, 0.f, 0.f);

    for (int it = 0; it < nIter; it++) {
        int p = r0 + it * 2 + half;
        bool valid = p < r1;
        int pp = valid ? p : (r1 - 1);
        int e = g_eidx[pp];
        int s = (e < E_RAW) ? ei[e] : (e - E_RAW);
        float4 xl = *(const float4*)(g_xl1 + (size_t)s * F1 + c);
        float v0 = xl.x + xr.x; v0 = v0 > 0.f ? v0 : 0.2f * v0;
        float v1 = xl.y + xr.y; v1 = v1 > 0.f ? v1 : 0.2f * v1;
        float v2 = xl.z + xr.z; v2 = v2 > 0.f ? v2 : 0.2f * v2;
        float v3 = xl.w + xr.w; v3 = v3 > 0.f ? v3 : 0.2f * v3;
        float sc = v0 * at.x + v1 * at.y + v2 * at.z + v3 * at.w;
        sc += __shfl_xor_sync(0xffffffffu, sc, 1);
        sc += __shfl_xor_sync(0xffffffffu, sc, 2);
        sc += __shfl_xor_sync(0xffffffffu, sc, 4);
        sc += __shfl_xor_sync(0xffffffffu, sc, 8);
        if (valid && sc > m) {
            float r = __expf(m - sc);
            den *= r; acc.x *= r; acc.y *= r; acc.z *= r; acc.w *= r; m = sc;
        }
        float a = valid ? __expf(sc - m) : 0.f;
        den += a;
        acc.x += a * xl.x; acc.y += a * xl.y; acc.z += a * xl.z; acc.w += a * xl.w;
    }

    float mo   = __shfl_xor_sync(0xffffffffu, m, 16);
    float deno = __shfl_xor_sync(0xffffffffu, den, 16);
    float4 ao;
    ao.x = __shfl_xor_sync(0xffffffffu, acc.x, 16);
    ao.y = __shfl_xor_sync(0xffffffffu, acc.y, 16);
    ao.z = __shfl_xor_sync(0xffffffffu, acc.z, 16);
    ao.w = __shfl_xor_sync(0xffffffffu, acc.w, 16);
    float M = fmaxf(m, mo);
    float sA = (m  > -INFINITY) ? __expf(m  - M) : 0.f;
    float sB = (mo > -INFINITY) ? __expf(mo - M) : 0.f;
    den = den * sA + deno * sB;
    acc.x = acc.x * sA + ao.x * sB;
    acc.y = acc.y * sA + ao.y * sB;
    acc.z = acc.z * sA + ao.z * sB;
    acc.w = acc.w * sA + ao.w * sB;

    if (half == 0) {
        float4 bb = *(const float4*)(b1 + c);
        float invd = 1.0f / den;
        float o0 = acc.x * invd + bb.x; o0 = o0 > 0.f ? o0 : __expf(o0) - 1.f;
        float o1 = acc.y * invd + bb.y; o1 = o1 > 0.f ? o1 : __expf(o1) - 1.f;
        float o2 = acc.z * invd + bb.z; o2 = o2 > 0.f ? o2 : __expf(o2) - 1.f;
        float o3 = acc.w * invd + bb.w; o3 = o3 > 0.f ? o3 : __expf(o3) - 1.f;
        __nv_bfloat16 h[4], lo[4];
        split2(o0, &h[0], &lo[0]); split2(o1, &h[1], &lo[1]);
        split2(o2, &h[2], &lo[2]); split2(o3, &h[3], &lo[3]);
        *(uint2*)(g_h1h  + (size_t)n * F1 + c) = *(const uint2*)h;
        *(uint2*)(g_h1lo + (size_t)n * F1 + c) = *(const uint2*)lo;
    }
}

// ---------------- fused GAT layer 2 + linear + elu (dual-edge) ----------------
__global__ void gat2_kernel(const int* __restrict__ ei, const float* __restrict__ att,
                            const float* __restrict__ b2,
                            const float* __restrict__ Wlin, const float* __restrict__ blin,
                            float* __restrict__ out)
{
    __shared__ float sW[64 * 32];
    __shared__ float sb[32];
    __shared__ float sh2[8][64];
    for (int i = threadIdx.x; i < 64 * 32; i += 256) sW[i] = Wlin[i];
    if (threadIdx.x < 32) sb[threadIdx.x] = blin[threadIdx.x];
    __syncthreads();

    int w = threadIdx.x >> 5, l = threadIdx.x & 31;
    int half = l >> 4, hl = l & 15;
    int n = blockIdx.x * 8 + w;
    int c = hl * 4;

    float4 xr = *(const float4*)(g_xr2 + (size_t)n * F2 + c);
    float4 at = *(const float4*)(att + c);

    int r0 = g_rowptr[n], r1 = g_rowptr[n + 1];
    int nIter = (r1 - r0 + 1) >> 1;
    float m = -INFINITY, den = 0.f;
    float4 acc = make_float4(0.f, 0.f, 0.f, 0.f);

    for (int it = 0; it < nIter; it++) {
        int p = r0 + it * 2 + half;
        bool valid = p < r1;
        int pp = valid ? p : (r1 - 1);
        int e = g_eidx[pp];
        int s = (e < E_RAW) ? ei[e] : (e - E_RAW);
        float4 xl = *(const float4*)(g_xl2 + (size_t)s * F2 + c);
        float v0 = xl.x + xr.x; v0 = v0 > 0.f ? v0 : 0.2f * v0;
        float v1 = xl.y + xr.y; v1 = v1 > 0.f ? v1 : 0.2f * v1;
        float v2 = xl.z + xr.z; v2 = v2 > 0.f ? v2 : 0.2f * v2;
        float v3 = xl.w + xr.w; v3 = v3 > 0.f ? v3 : 0.2f * v3;
        float sc = v0 * at.x + v1 * at.y + v2 * at.z + v3 * at.w;
        sc += __shfl_xor_sync(0xffffffffu, sc, 1);
        sc += __shfl_xor_sync(0xffffffffu, sc, 2);
        sc += __shfl_xor_sync(0xffffffffu, sc, 4);
        sc += __shfl_xor_sync(0xffffffffu, sc, 8);
        if (valid && sc > m) {
            float r = __expf(m - sc);
            den *= r; acc.x *= r; acc.y *= r; acc.z *= r; acc.w *= r; m = sc;
        }
        float a = valid ? __expf(sc - m) : 0.f;
        den += a;
        acc.x += a * xl.x; acc.y += a * xl.y; acc.z += a * xl.z; acc.w += a * xl.w;
    }

    float mo   = __shfl_xor_sync(0xffffffffu, m, 16);
    float deno = __shfl_xor_sync(0xffffffffu, den, 16);
    float4 ao;
    ao.x = __shfl_xor_sync(0xffffffffu, acc.x, 16);
    ao.y = __shfl_xor_sync(0xffffffffu, acc.y, 16);
    ao.z = __shfl_xor_sync(0xffffffffu, acc.z, 16);
    ao.w = __shfl_xor_sync(0xffffffffu, acc.w, 16);
    float M = fmaxf(m, mo);
    float sA = (m  > -INFINITY) ? __expf(m  - M) : 0.f;
    float sB = (mo > -INFINITY) ? __expf(mo - M) : 0.f;
    den = den * sA + deno * sB;
    acc.x = acc.x * sA + ao.x * sB;
    acc.y = acc.y * sA + ao.y * sB;
    acc.z = acc.z * sA + ao.z * sB;
    acc.w = acc.w * sA + ao.w * sB;

    if (half == 0) {
        float4 bb = *(const float4*)(b2 + c);
        float invd = 1.0f / den;
        float h0 = acc.x * invd + bb.x; h0 = h0 > 0.f ? h0 : __expf(h0) - 1.f;
        float h1 = acc.y * invd + bb.y; h1 = h1 > 0.f ? h1 : __expf(h1) - 1.f;
        float h2 = acc.z * invd + bb.z; h2 = h2 > 0.f ? h2 : __expf(h2) - 1.f;
        float h3 = acc.w * invd + bb.w; h3 = h3 > 0.f ? h3 : __expf(h3) - 1.f;
        sh2[w][c] = h0; sh2[w][c + 1] = h1; sh2[w][c + 2] = h2; sh2[w][c + 3] = h3;
    }
    __syncwarp();

    float o = sb[l];
    #pragma unroll
    for (int k = 0; k < 64; k++) o += sh2[w][k] * sW[k * 32 + l];
    out[(size_t)n * OUTF + l] = o > 0.f ? o : __expf(o) - 1.f;
}

// ---------------- launch ------------------------------------------------------
extern "C" void kernel_launch(void* const* d_in, const int* in_sizes, int n_in,
                              void* d_out, int out_size) {
    const float* x    = (const float*)d_in[0];
    const int*   ei   = (const int*)  d_in[1];
    const float* W1l  = (const float*)d_in[2];
    const float* W1r  = (const float*)d_in[3];
    const float* att1 = (const float*)d_in[4];
    const float* b1   = (const float*)d_in[5];
    const float* W2l  = (const float*)d_in[6];
    const float* W2r  = (const float*)d_in[7];
    const float* att2 = (const float*)d_in[8];
    const float* b2   = (const float*)d_in[9];
    const float* Wlin = (const float*)d_in[10];
    const float* blin = (const float*)d_in[11];
    float* out = (float*)d_out;

    float *p_xl1, *p_xr1, *p_xl2, *p_xr2;
    int* p_deg;
    __nv_bfloat16 *p_xh, *p_xlo, *p_w1h, *p_w1lo, *p_h1h, *p_h1lo, *p_w2h, *p_w2lo;
    cudaGetSymbolAddress((void**)&p_xl1,  g_xl1);
    cudaGetSymbolAddress((void**)&p_xr1,  g_xr1);
    cudaGetSymbolAddress((void**)&p_xl2,  g_xl2);
    cudaGetSymbolAddress((void**)&p_xr2,  g_xr2);
    cudaGetSymbolAddress((void**)&p_deg,  g_deg);
    cudaGetSymbolAddress((void**)&p_xh,   g_xh);
    cudaGetSymbolAddress((void**)&p_xlo,  g_xlo);
    cudaGetSymbolAddress((void**)&p_w1h,  g_w1h);
    cudaGetSymbolAddress((void**)&p_w1lo, g_w1lo);
    cudaGetSymbolAddress((void**)&p_h1h,  g_h1h);
    cudaGetSymbolAddress((void**)&p_h1lo, g_h1lo);
    cudaGetSymbolAddress((void**)&p_w2h,  g_w2h);
    cudaGetSymbolAddress((void**)&p_w2lo, g_w2lo);

    // one-time resources (host-side only; no device allocations)
    static cudaStream_t s2 = nullptr;
    static cudaEvent_t evFork = nullptr, evJoin = nullptr;
    if (s2 == nullptr) {
        cudaStreamCreateWithFlags(&s2, cudaStreamNonBlocking);
        cudaEventCreateWithFlags(&evFork, cudaEventDisableTiming);
        cudaEventCreateWithFlags(&evJoin, cudaEventDisableTiming);
    }

    // fork: CSR chain on s2, splits+GEMM1 on main stream
    cudaEventRecord(evFork, 0);
    cudaStreamWaitEvent(s2, evFork, 0);

    // --- branch A (s2): CSR build ---
    cudaMemsetAsync(p_deg, 0, N_NODES * sizeof(int), s2);
    count_kernel<<<(E_TOT + 255) / 256, 256, 0, s2>>>(ei);
    int nblk = (N_NODES + 1023) / 1024;
    scan1_kernel<<<nblk, 1024, 0, s2>>>();
    scan23_kernel<<<(N_NODES + 255) / 256, 256, 0, s2>>>();
    scatter_kernel<<<(E_TOT + 255) / 256, 256, 0, s2>>>(ei);
    cudaEventRecord(evJoin, s2);

    // --- branch B (main): splits + layer-1 GEMM ---
    split_x_kernel<<<(N_NODES * D_IN + 255) / 256, 256>>>(x);
    split_w_kernel<<<(F1 * D_IN + F2 * F1 + 255) / 256, 256>>>(W1l, W1r, W2l, W2r);
    gemm_mma<<<dim3(16, (N_NODES + 127) / 128), 256>>>(
        p_xh, p_xlo, p_w1h, p_w1lo, p_xl1, p_xr1, N_NODES, F1, D_IN, 8);

    // join, then edge phase
    cudaStreamWaitEvent(0, evJoin, 0);
    gat1_kernel<<<N_NODES, 256>>>(ei, att1, b1);

    gemm_mma<<<dim3(2, (N_NODES + 127) / 128), 256>>>(
        p_h1h, p_h1lo, p_w2h, p_w2lo, p_xl2, p_xr2, N_NODES, F2, F1, 1);
    gat2_kernel<<<N_NODES / 8, 256>>>(ei, att2, b2, Wlin, blin, out);
}